// round 5
// baseline (speedup 1.0000x reference)
#include <cuda_runtime.h>
#include <stdint.h>

// Problem constants (shapes fixed by the reference)
#define BB 32
#define TT 256
#define DD 384
#define ML 2048
#define D4 (DD / 4)   // 96 float4 per row

// Scratch: per-frame source-token index (-1 => invalid/zero)
__device__ int g_idx[BB * ML];

// Kernel 1: per-batch inclusive scan of durations, then SCATTER:
// token t covers frames [csum[t-1], csum[t]) -> write t there. Exactly
// reproduces searchsorted(csum, f, side='right') for all valid frames
// (zero-duration tokens write nothing). Verified EXACT in R4 (output-0
// rel_err = 0).
//
// Duration dtype auto-detected (int32 vs int64), validated in R2/R4:
// viewed as int32 words, an int64 buffer of values in [0,8) has ALL
// odd-indexed words == 0 (high words); an int32 buffer has real durations
// at odd indices. Probe touches words [0,512) — in-bounds either way.
__global__ void lr_scan_kernel(const int* __restrict__ dur32,
                               float* __restrict__ mel_out) {
    __shared__ int cs[TT];
    const int b = blockIdx.x;
    const int t = threadIdx.x;

    // dtype probe (block-uniform, deterministic)
    const int odd_word = dur32[2 * t + 1];
    const int is_int32 = __syncthreads_or(odd_word != 0);

    cs[t] = is_int32 ? dur32[b * TT + t]          // int32 layout
                     : dur32[2 * (b * TT + t)];   // int64 low word
    __syncthreads();

    // Hillis-Steele inclusive scan over 256 elements
    #pragma unroll
    for (int off = 1; off < TT; off <<= 1) {
        int add = (t >= off) ? cs[t - off] : 0;
        __syncthreads();
        cs[t] += add;
        __syncthreads();
    }

    const int mel = cs[TT - 1];
    // mel_len tail is interpreted as float32 by the harness (proven in R2-R4).
    if (t == 0 && mel_out != nullptr) mel_out[b] = (float)mel;

    // Pre-fill all frames with -1 (tail [mel, ML) remains -1 after scatter).
    for (int f = t; f < ML; f += TT) g_idx[b * ML + f] = -1;
    __syncthreads();

    // Scatter: this thread's token covers [start, end), intervals disjoint.
    const int end   = cs[t];
    const int start = (t == 0) ? 0 : cs[t - 1];
    for (int f = start; f < end; f++) g_idx[b * ML + f] = t;
}

// Kernel 2: gather/expand. One float4 per thread; 96 lanes cover one D-row,
// 4 rows per 384-thread block. Writes fully coalesced. x (12 MB) is
// L2-resident; this kernel is HBM-store-bound (~100 MB).
__global__ void lr_gather_kernel(const float4* __restrict__ x,
                                 float4* __restrict__ out) {
    const int row = blockIdx.x * 4 + threadIdx.y;   // 0 .. B*ML-1
    const int j   = threadIdx.x;                    // 0 .. 95
    const int b   = row >> 11;                      // row / 2048
    const int idx = g_idx[row];

    float4 v = make_float4(0.f, 0.f, 0.f, 0.f);
    if (idx >= 0) v = __ldg(&x[(b * TT + idx) * D4 + j]);
    out[(long long)row * D4 + j] = v;
}

extern "C" void kernel_launch(void* const* d_in, const int* in_sizes, int n_in,
                              void* d_out, int out_size) {
    const float* x     = (const float*)d_in[0];
    const int*   dur32 = (const int*)d_in[1];   // int32 OR int64 (autodetected)
    // d_in[2] = max_len (scalar, constant 2048)

    float* out = (float*)d_out;
    const long long main_elems = (long long)BB * ML * DD;
    const long long extra = (long long)out_size - main_elems;

    float* mel_out = (extra > 0) ? (out + main_elems) : nullptr;

    lr_scan_kernel<<<BB, TT>>>(dur32, mel_out);

    dim3 blk(D4, 4);
    dim3 grd((BB * ML) / 4);
    lr_gather_kernel<<<grd, blk>>>((const float4*)x, (float4*)out);
}

// round 6
// speedup vs baseline: 1.1028x; 1.1028x over previous
#include <cuda_runtime.h>
#include <stdint.h>

// Problem constants (shapes fixed by the reference)
#define BB 32
#define TT 256
#define DD 384
#define ML 2048
#define D4 (DD / 4)   // 96 float4 per row
#define RPT 4         // rows per thread in gather

// Scratch: per-frame source-token index (-1 => invalid/zero)
__device__ int g_idx[BB * ML];

// Kernel 1: per-batch inclusive scan of durations, then SCATTER:
// token t covers frames [csum[t-1], csum[t]) -> write t there. Exact
// searchsorted(csum, f, side='right') semantics (verified rel_err=0 in R4/R5).
//
// Duration dtype auto-detected (int32 vs int64): viewed as int32 words, an
// int64 buffer of values in [0,8) has ALL odd words == 0; an int32 buffer has
// real durations at odd indices. Probe touches words [0,512) — in-bounds
// under both interpretations.
__global__ void lr_scan_kernel(const int* __restrict__ dur32,
                               float* __restrict__ mel_out) {
    __shared__ int cs[TT];
    const int b = blockIdx.x;
    const int t = threadIdx.x;

    const int odd_word = dur32[2 * t + 1];
    const int is_int32 = __syncthreads_or(odd_word != 0);

    cs[t] = is_int32 ? dur32[b * TT + t]          // int32 layout
                     : dur32[2 * (b * TT + t)];   // int64 low word
    __syncthreads();

    // Hillis-Steele inclusive scan over 256 elements
    #pragma unroll
    for (int off = 1; off < TT; off <<= 1) {
        int add = (t >= off) ? cs[t - off] : 0;
        __syncthreads();
        cs[t] += add;
        __syncthreads();
    }

    const int mel = cs[TT - 1];
    // mel_len tail is float32 (proven R4->R5).
    if (t == 0 && mel_out != nullptr) mel_out[b] = (float)mel;

    // Pre-fill all frames with -1 (tail [mel, ML) remains -1 after scatter).
    for (int f = t; f < ML; f += TT) g_idx[b * ML + f] = -1;
    __syncthreads();

    // Scatter: this thread's token covers [start, end), intervals disjoint.
    const int end   = cs[t];
    const int start = (t == 0) ? 0 : cs[t - 1];
    for (int f = start; f < end; f++) g_idx[b * ML + f] = t;
}

// Kernel 2: gather/expand with 4-way ILP. Each thread handles RPT=4
// consecutive rows at one j lane: 4 batched idx loads (warp-uniform addr ->
// L1 broadcast), 4 independent gather loads (MLP=4), 4 coalesced stores.
// 4-row groups never straddle a batch boundary (ML % 4 == 0).
__global__ void lr_gather_kernel(const float4* __restrict__ x,
                                 float4* __restrict__ out) {
    const int j    = threadIdx.x;                         // 0..95
    const int rg   = blockIdx.x * 4 + threadIdx.y;        // row-group id
    const int row0 = rg * RPT;                            // first of 4 rows
    const int b    = row0 >> 11;                          // row / 2048

    int idx[RPT];
    #pragma unroll
    for (int i = 0; i < RPT; i++) idx[i] = g_idx[row0 + i];

    float4 v[RPT];
    #pragma unroll
    for (int i = 0; i < RPT; i++) {
        v[i] = make_float4(0.f, 0.f, 0.f, 0.f);
        if (idx[i] >= 0) v[i] = __ldg(&x[(b * TT + idx[i]) * D4 + j]);
    }

    const long long base = (long long)row0 * D4 + j;
    #pragma unroll
    for (int i = 0; i < RPT; i++) out[base + (long long)i * D4] = v[i];
}

extern "C" void kernel_launch(void* const* d_in, const int* in_sizes, int n_in,
                              void* d_out, int out_size) {
    const float* x     = (const float*)d_in[0];
    const int*   dur32 = (const int*)d_in[1];   // int32 OR int64 (autodetected)
    // d_in[2] = max_len (scalar, constant 2048)

    float* out = (float*)d_out;
    const long long main_elems = (long long)BB * ML * DD;
    const long long extra = (long long)out_size - main_elems;

    float* mel_out = (extra > 0) ? (out + main_elems) : nullptr;

    lr_scan_kernel<<<BB, TT>>>(dur32, mel_out);

    dim3 blk(D4, 4);                          // 384 threads
    dim3 grd((BB * ML) / (4 * RPT));          // 4096 blocks
    lr_gather_kernel<<<grd, blk>>>((const float4*)x, (float4*)out);
}

// round 7
// speedup vs baseline: 1.1860x; 1.0754x over previous
#include <cuda_runtime.h>
#include <stdint.h>

// Problem constants (fixed by the reference)
#define BB 32
#define TT 256
#define DD 384
#define ML 2048
#define D4 (DD / 4)   // 96 float4 per row
#define RPT 8         // rows per thread
#define RPB 32        // rows per block = 4 y-slices * RPT

// Single fused kernel. Block = (96,4) = 384 threads; each block handles RPB=32
// consecutive output rows of one batch (ML % RPB == 0, so never straddles a
// batch). Prelude: scan this batch's durations (int32 — established R1..R5),
// scatter the block's 32-row idx window into smem, then 8-way-ILP gather.
__global__ void lr_fused_kernel(const float4* __restrict__ x,
                                const int* __restrict__ dur,
                                float4* __restrict__ out,
                                float* __restrict__ mel_out) {
    __shared__ int cs[TT];         // inclusive cumsum of durations
    __shared__ int sidx[RPB];      // source-token idx for block's rows (-1 = pad)

    const int tid = threadIdx.y * blockDim.x + threadIdx.x;  // 0..383
    const int r0  = blockIdx.x * RPB;        // first output row of this block
    const int b   = r0 >> 11;                // batch = r0 / ML
    const int rloc = r0 & (ML - 1);          // row offset within batch

    // ---- prelude: load durations + init idx window ----
    if (tid < TT) cs[tid] = dur[b * TT + tid];
    else if (tid < TT + RPB) sidx[tid - TT] = -1;
    __syncthreads();

    // Hillis-Steele inclusive scan over 256 (all 384 threads hit the syncs)
    #pragma unroll
    for (int off = 1; off < TT; off <<= 1) {
        int add = (tid >= off && tid < TT) ? cs[tid - off] : 0;
        __syncthreads();
        if (tid < TT) cs[tid] += add;
        __syncthreads();
    }

    // mel_len (float32 tail — proven in R4->R5); one block per batch writes it
    if (rloc == 0 && tid == 0 && mel_out != nullptr)
        mel_out[b] = (float)cs[TT - 1];

    // Scatter this block's 32-row window: token tid covers [start, end)
    if (tid < TT) {
        const int end   = cs[tid];
        const int start = (tid == 0) ? 0 : cs[tid - 1];
        int lo = start > rloc ? start : rloc;
        int hi = end < rloc + RPB ? end : rloc + RPB;
        for (int f = lo; f < hi; f++) sidx[f - rloc] = tid;
    }
    __syncthreads();

    // ---- gather: 8 rows per thread, MLP=8 ----
    const int j  = threadIdx.x;                    // 0..95
    const int ry = threadIdx.y * RPT;              // this thread's first local row

    int idx[RPT];
    #pragma unroll
    for (int i = 0; i < RPT; i++) idx[i] = sidx[ry + i];

    float4 v[RPT];
    #pragma unroll
    for (int i = 0; i < RPT; i++) {
        v[i] = make_float4(0.f, 0.f, 0.f, 0.f);
        if (idx[i] >= 0) v[i] = __ldg(&x[(b * TT + idx[i]) * D4 + j]);
    }

    const long long base = (long long)(r0 + ry) * D4 + j;
    #pragma unroll
    for (int i = 0; i < RPT; i++) out[base + (long long)i * D4] = v[i];
}

extern "C" void kernel_launch(void* const* d_in, const int* in_sizes, int n_in,
                              void* d_out, int out_size) {
    const float* x   = (const float*)d_in[0];
    const int*   dur = (const int*)d_in[1];   // harness stores duration as int32
    // d_in[2] = max_len (scalar, constant 2048)

    float* out = (float*)d_out;
    const long long main_elems = (long long)BB * ML * DD;
    const long long extra = (long long)out_size - main_elems;
    float* mel_out = (extra > 0) ? (out + main_elems) : nullptr;

    dim3 blk(D4, 4);                     // 384 threads
    dim3 grd((BB * ML) / RPB);           // 2048 blocks
    lr_fused_kernel<<<grd, blk>>>((const float4*)x, dur, (float4*)out, mel_out);
}